// round 12
// baseline (speedup 1.0000x reference)
#include <cuda_runtime.h>
#include <cuda_bf16.h>
#include <cstdint>

#define Tz 512
#define Bz 32
#define Iz 256
#define Hz 512
#define Gz 2048          // 4*H
#define TB (Tz*Bz)       // 16384

// -------- scratch (device globals; no runtime allocation) --------
__device__ float g_xt[(size_t)TB * Iz];        // x transposed to [T,B,I]
__device__ float g_xg0[(size_t)TB * Gz];       // fwd-dir input-gate projections
__device__ float g_xg1[(size_t)TB * Gz];       // bwd-dir input-gate projections
__device__ float g_y0[(size_t)TB * 2 * Hz];    // layer-0 output [T,B,2H]
__device__ uint2 g_hq[2][2][Bz * Hz];          // [dir][parity][b*512+u] {(hi<<16)|lo, tag}
__device__ float g_cbuf[2][Bz * Hz];           // [dir][b*H+u]

__device__ __forceinline__ float sigf(float x) { return 1.f / (1.f + __expf(-x)); }
__device__ __forceinline__ float tanhf_(float x) { return 2.f / (1.f + __expf(-2.f * x)) - 1.f; }

__device__ __forceinline__ uint32_t f2tf32(float f) {
    uint32_t r;
    asm("cvt.rna.tf32.f32 %0, %1;" : "=r"(r) : "f"(f));
    return r;
}

__device__ __forceinline__ uint32_t smem_u32(const void* p) {
    uint32_t a;
    asm("{ .reg .u64 t; cvta.to.shared.u64 t, %1; cvt.u32.u64 %0, t; }" : "=r"(a) : "l"(p));
    return a;
}

// mma.sync tf32 m16n8k8 (input GEMMs)
__device__ __forceinline__ void mma_tf32(float* c, const uint32_t* a,
                                         uint32_t b0, uint32_t b1) {
    asm volatile(
        "mma.sync.aligned.m16n8k8.row.col.f32.tf32.tf32.f32 "
        "{%0,%1,%2,%3}, {%4,%5,%6,%7}, {%8,%9}, {%0,%1,%2,%3};"
        : "+f"(c[0]), "+f"(c[1]), "+f"(c[2]), "+f"(c[3])
        : "r"(a[0]), "r"(a[1]), "r"(a[2]), "r"(a[3]), "r"(b0), "r"(b1));
}

// mma.sync bf16 m16n8k16 (recurrence)
__device__ __forceinline__ void mma_bf16(float* c, const uint32_t* a,
                                         uint32_t b0, uint32_t b1) {
    asm volatile(
        "mma.sync.aligned.m16n8k16.row.col.f32.bf16.bf16.f32 "
        "{%0,%1,%2,%3}, {%4,%5,%6,%7}, {%8,%9}, {%0,%1,%2,%3};"
        : "+f"(c[0]), "+f"(c[1]), "+f"(c[2]), "+f"(c[3])
        : "r"(a[0]), "r"(a[1]), "r"(a[2]), "r"(a[3]), "r"(b0), "r"(b1));
}

#define LDSM2(d0, d1, a)                                                        \
    asm volatile("ldmatrix.sync.aligned.m8n8.x2.shared.b16 {%0,%1}, [%2];"      \
                 : "=r"(d0), "=r"(d1) : "r"(a))
#define LDGV4(v, p)                                                             \
    asm volatile("ld.global.cg.v4.u32 {%0,%1,%2,%3}, [%4];"                     \
                 : "=r"((v).x), "=r"((v).y), "=r"((v).z), "=r"((v).w)           \
                 : "l"(p))
#define STGV2(p, v)                                                             \
    asm volatile("st.global.cg.v2.u32 [%0], {%1,%2};"                           \
                 :: "l"(p), "r"((v).x), "r"((v).y) : "memory")

// -------- transpose x [B,I,T] -> xt [T,B,I] --------
__global__ void transpose_x(const float* __restrict__ x) {
    __shared__ float tile[32][33];
    int b = blockIdx.z, i0 = blockIdx.y * 32, t0 = blockIdx.x * 32;
    int tx = threadIdx.x, ty = threadIdx.y;
#pragma unroll
    for (int r = ty; r < 32; r += 8)
        tile[r][tx] = x[(size_t)b * Iz * Tz + (size_t)(i0 + r) * Tz + t0 + tx];
    __syncthreads();
#pragma unroll
    for (int r = ty; r < 32; r += 8)
        g_xt[(size_t)(t0 + r) * Bz * Iz + (size_t)b * Iz + i0 + tx] = tile[tx][r];
}

// ======== tf32 mma.sync GEMM: C[M,Gz] = A[M,K] @ W[Gz,K]^T + bi + bh ========
__global__ __launch_bounds__(256) void gemm_xg_mma(
    const float* __restrict__ A, const float* __restrict__ W,
    const float* __restrict__ bi, const float* __restrict__ bh,
    float* __restrict__ C, int K)
{
    __shared__ uint32_t As[128 * 36];
    __shared__ uint32_t Bs[128 * 36];

    int tid = threadIdx.x;
    int wid = tid >> 5, lane = tid & 31;
    int gid = lane >> 2, tig = lane & 3;
    int n0 = blockIdx.x * 128, m0 = blockIdx.y * 128;
    int mwarp = (wid >> 1) * 32;
    int nwarp = (wid & 1) * 64;
    int lrow = tid >> 3, lq = tid & 7;

    float c[2][8][4];
#pragma unroll
    for (int mt = 0; mt < 2; mt++)
#pragma unroll
        for (int nt = 0; nt < 8; nt++)
#pragma unroll
            for (int q = 0; q < 4; q++) c[mt][nt][q] = 0.f;

    float4 pa[4], pb[4];
#pragma unroll
    for (int j = 0; j < 4; j++) {
        pa[j] = *(const float4*)&A[(size_t)(m0 + lrow + j * 32) * K + lq * 4];
        pb[j] = *(const float4*)&W[(size_t)(n0 + lrow + j * 32) * K + lq * 4];
    }

    for (int k0 = 0; k0 < K; k0 += 32) {
#pragma unroll
        for (int j = 0; j < 4; j++) {
            uint4 ta, tb;
            ta.x = f2tf32(pa[j].x); ta.y = f2tf32(pa[j].y);
            ta.z = f2tf32(pa[j].z); ta.w = f2tf32(pa[j].w);
            tb.x = f2tf32(pb[j].x); tb.y = f2tf32(pb[j].y);
            tb.z = f2tf32(pb[j].z); tb.w = f2tf32(pb[j].w);
            *(uint4*)&As[(lrow + j * 32) * 36 + lq * 4] = ta;
            *(uint4*)&Bs[(lrow + j * 32) * 36 + lq * 4] = tb;
        }
        __syncthreads();

        if (k0 + 32 < K) {
#pragma unroll
            for (int j = 0; j < 4; j++) {
                pa[j] = *(const float4*)&A[(size_t)(m0 + lrow + j * 32) * K + k0 + 32 + lq * 4];
                pb[j] = *(const float4*)&W[(size_t)(n0 + lrow + j * 32) * K + k0 + 32 + lq * 4];
            }
        }

#pragma unroll
        for (int kk = 0; kk < 32; kk += 8) {
            uint32_t a[2][4];
#pragma unroll
            for (int mt = 0; mt < 2; mt++) {
                int mrow = mwarp + mt * 16;
                a[mt][0] = As[(mrow + gid)     * 36 + kk + tig];
                a[mt][1] = As[(mrow + gid + 8) * 36 + kk + tig];
                a[mt][2] = As[(mrow + gid)     * 36 + kk + tig + 4];
                a[mt][3] = As[(mrow + gid + 8) * 36 + kk + tig + 4];
            }
#pragma unroll
            for (int nt = 0; nt < 8; nt++) {
                uint32_t b0 = Bs[(nwarp + nt * 8 + gid) * 36 + kk + tig];
                uint32_t b1 = Bs[(nwarp + nt * 8 + gid) * 36 + kk + tig + 4];
                mma_tf32(c[0][nt], a[0], b0, b1);
                mma_tf32(c[1][nt], a[1], b0, b1);
            }
        }
        __syncthreads();
    }

#pragma unroll
    for (int mt = 0; mt < 2; mt++) {
        int m = m0 + mwarp + mt * 16 + gid;
#pragma unroll
        for (int nt = 0; nt < 8; nt++) {
            int n = n0 + nwarp + nt * 8 + 2 * tig;
            float bs0 = bi[n] + bh[n];
            float bs1 = bi[n + 1] + bh[n + 1];
            float2 o0 = {c[mt][nt][0] + bs0, c[mt][nt][1] + bs1};
            float2 o1 = {c[mt][nt][2] + bs0, c[mt][nt][3] + bs1};
            *(float2*)&C[(size_t)m * Gz + n] = o0;
            *(float2*)&C[(size_t)(m + 8) * Gz + n] = o1;
        }
    }
}

// ======== persistent recurrence — K-split bf16, tag-in-data sync ========
// h elements carry their step tag in the same 8B word-pair; consumers LDG.128
// fragments directly from L2 and retry stale ones. No flags, no fences.
#define RST 1040                      // W smem row stride bytes (520 bf16)
#define RSM_WHI 0                     // [32 c][520]
#define RSM_WLO 33280
#define RSM_PS  66560                 // float[8][32][40]
#define REC_SMEM_BYTES (66560 + 8 * 32 * 40 * 4)

__global__ __launch_bounds__(256, 1) void lstm_rec(
    const float* __restrict__ Wf, const float* __restrict__ Wb,
    float* __restrict__ outbuf, int st_t, int st_b, unsigned epoch)
{
    extern __shared__ char smr[];
    uint32_t sbase = smem_u32(smr);

    int dir = blockIdx.x & 1;
    int cb = blockIdx.x >> 1;
    int u0 = cb * 8;
    const float* W = dir ? Wb : Wf;
    const float* xg = dir ? g_xg1 : g_xg0;
    int tid = threadIdx.x;
    int wid = tid >> 5, l = tid & 31;
    int gid = l >> 2, tig = l & 3;

    // ---- split this CTA's 32 W_hh rows into bf16 hi/lo SMEM planes (once) ----
    {
        int c = tid >> 3, kq = tid & 7;
        const float* wrow = W + (size_t)((c >> 3) * Hz + u0 + (c & 7)) * Hz;
        unsigned short* whi = (unsigned short*)(smr + RSM_WHI);
        unsigned short* wlo = (unsigned short*)(smr + RSM_WLO);
#pragma unroll 4
        for (int p = 0; p < 16; p++) {
            int k = p * 32 + kq * 4;
            float4 v = *(const float4*)&wrow[k];
            float vv[4] = {v.x, v.y, v.z, v.w};
#pragma unroll
            for (int j = 0; j < 4; j++) {
                __nv_bfloat16 hb = __float2bfloat16(vv[j]);
                whi[c * 520 + k + j] = __bfloat16_as_ushort(hb);
                wlo[c * 520 + k + j] = __bfloat16_as_ushort(
                    __float2bfloat16(vv[j] - __bfloat162float(hb)));
            }
        }
    }

    // ---- publish h(0): zero data + epoch tag (this CTA's 1/64 chunk) ----
    {
        uint2 iv; iv.x = 0u; iv.y = epoch;
        STGV2(&g_hq[dir][0][cb * 256 + tid], iv);
    }
    float creg = 0.f;
    __syncthreads();   // W planes ready before per-step ldmatrix

    uint32_t bbase = sbase + RSM_WHI + (uint32_t)(l & 7) * RST
                   + (uint32_t)(((l >> 3) & 1) * 16) + (uint32_t)wid * 128;
    float* ps = (float*)(smr + RSM_PS);
    int bb = tid >> 3, uul = tid & 7;          // this thread's (batch, unit)

    // prefetch xg for step 0
    float xv[4];
    {
        int t0v = dir ? (Tz - 1) : 0;
        const float* xr = xg + (size_t)t0v * Bz * Gz + (size_t)bb * Gz + u0 + uul;
        xv[0] = xr[0 * Hz]; xv[1] = xr[1 * Hz]; xv[2] = xr[2 * Hz]; xv[3] = xr[3 * Hz];
    }

    int kcb = wid * 64 + 2 * tig;              // this lane's base k column

    for (int s = 0; s < Tz; s++) {
        int rb = s & 1;
        int wb = rb ^ 1;
        int t = dir ? (Tz - 1 - s) : s;
        unsigned tg = epoch + (unsigned)s;

        // ---- tag-validated fragment loads (retry only stale) ----
        const uint2* hp = g_hq[dir][rb];
        uint2 wv2[4][8];
        unsigned mask = 0xFFFFFFFFu;
        do {
#pragma unroll
            for (int ki = 0; ki < 4; ki++) {
                int kc = kcb + ki * 16;
#pragma unroll
                for (int j = 0; j < 8; j++) {
                    unsigned bit = 1u << (ki * 8 + j);
                    if (mask & bit) {
                        int r = ((j >> 2) * 16) + gid + ((j & 1) ? 8 : 0);
                        int kcol = kc + ((j & 2) ? 8 : 0);
                        uint4 v;
                        LDGV4(v, (const uint4*)&hp[(size_t)r * 512 + kcol]);
                        if (v.y == tg && v.w == tg) {
                            wv2[ki][j].x = v.x;
                            wv2[ki][j].y = v.z;
                            mask &= ~bit;
                        }
                    }
                }
            }
        } while (__any_sync(0xFFFFFFFFu, mask));

        // ---- partial gates: 32b x 32cols over this warp's k64, 3-mma split ----
        float c[2][4][4];
#pragma unroll
        for (int mt = 0; mt < 2; mt++)
#pragma unroll
            for (int nt = 0; nt < 4; nt++)
#pragma unroll
                for (int q = 0; q < 4; q++) c[mt][nt][q] = 0.f;

#pragma unroll
        for (int ki = 0; ki < 4; ki++) {
            uint32_t ah[8], al[8];
#pragma unroll
            for (int j = 0; j < 8; j++) {
                ah[j] = __byte_perm(wv2[ki][j].x, wv2[ki][j].y, 0x7632);
                al[j] = __byte_perm(wv2[ki][j].x, wv2[ki][j].y, 0x5410);
            }
#pragma unroll
            for (int nt = 0; nt < 4; nt++) {
                uint32_t bh0, bh1, bl0, bl1;
                LDSM2(bh0, bh1, bbase + nt * 8 * RST + ki * 32);
                LDSM2(bl0, bl1, bbase + 33280 + nt * 8 * RST + ki * 32);
                mma_bf16(c[0][nt], ah,     bh0, bh1);
                mma_bf16(c[1][nt], ah + 4, bh0, bh1);
                mma_bf16(c[0][nt], ah,     bl0, bl1);
                mma_bf16(c[1][nt], ah + 4, bl0, bl1);
                mma_bf16(c[0][nt], al,     bh0, bh1);
                mma_bf16(c[1][nt], al + 4, bh0, bh1);
            }
        }

        // ---- scatter partials to ps[wid][32][40] ----
        {
            float* pw = ps + wid * (32 * 40);
#pragma unroll
            for (int nt = 0; nt < 4; nt++) {
                int col = nt * 8 + 2 * tig;
                float2 v;
                v.x = c[0][nt][0]; v.y = c[0][nt][1];
                *(float2*)&pw[(gid)      * 40 + col] = v;
                v.x = c[0][nt][2]; v.y = c[0][nt][3];
                *(float2*)&pw[(gid + 8)  * 40 + col] = v;
                v.x = c[1][nt][0]; v.y = c[1][nt][1];
                *(float2*)&pw[(gid + 16) * 40 + col] = v;
                v.x = c[1][nt][2]; v.y = c[1][nt][3];
                *(float2*)&pw[(gid + 24) * 40 + col] = v;
            }
        }
        __syncthreads();

        // ---- reduce 8 partials + gates + state update; store h with tag ----
        float hn;
        {
            float gv4[4];
#pragma unroll
            for (int g = 0; g < 4; g++) {
                int base = bb * 40 + g * 8 + uul;
                float acc = xv[g];
#pragma unroll
                for (int w = 0; w < 8; w++) acc += ps[base + w * 1280];
                gv4[g] = acc;
            }
            float iv = sigf(gv4[0]), fv = sigf(gv4[1]);
            float gg = tanhf_(gv4[2]), ov = sigf(gv4[3]);
            float cn = fv * creg + iv * gg;
            hn = ov * tanhf_(cn);
            creg = cn;
            __nv_bfloat16 hb = __float2bfloat16(hn);
            unsigned hi = __bfloat16_as_ushort(hb);
            unsigned lo = __bfloat16_as_ushort(
                __float2bfloat16(hn - __bfloat162float(hb)));
            uint2 ov2;
            ov2.x = (hi << 16) | lo;
            ov2.y = epoch + (unsigned)(s + 1);
            STGV2(&g_hq[dir][wb][bb * 512 + u0 + uul], ov2);
        }

        // off-critical-path: output store + next-step xg prefetch
        outbuf[(size_t)t * st_t + (size_t)bb * st_b + dir * Hz + u0 + uul] = hn;
        if (s + 1 < Tz) {
            int tn = dir ? (Tz - 2 - s) : (s + 1);
            const float* xr = xg + (size_t)tn * Bz * Gz + (size_t)bb * Gz + u0 + uul;
            xv[0] = xr[0 * Hz]; xv[1] = xr[1 * Hz];
            xv[2] = xr[2 * Hz]; xv[3] = xr[3 * Hz];
        }
        __syncthreads();   // protect ps from next step's scatter
    }

    g_cbuf[dir][bb * Hz + u0 + uul] = creg;
}

// -------- copy final h/c into h_n / c_n sections of d_out --------
__global__ void copy_state(float* __restrict__ dout, int layer) {
    int idx = blockIdx.x * 256 + threadIdx.x;   // 0..32767
    int d = idx >> 14;
    int r = idx & 16383;           // r = b*512 + u
    const size_t OUT = (size_t)Bz * Tz * 2 * Hz;
    unsigned w = g_hq[d][0][r].x;
    float hv = __bfloat162float(__ushort_as_bfloat16((unsigned short)(w >> 16)))
             + __bfloat162float(__ushort_as_bfloat16((unsigned short)(w & 0xFFFFu)));
    dout[OUT + (size_t)(2 * layer + d) * (Bz * Hz) + r] = hv;
    dout[OUT + 4 * (size_t)(Bz * Hz) + (size_t)(2 * layer + d) * (Bz * Hz) + r] = g_cbuf[d][r];
}

extern "C" void kernel_launch(void* const* d_in, const int* in_sizes, int n_in,
                              void* d_out, int out_size)
{
    const float* x        = (const float*)d_in[0];
    const float* w_ih_l0  = (const float*)d_in[1];
    const float* w_hh_l0  = (const float*)d_in[2];
    const float* b_ih_l0  = (const float*)d_in[3];
    const float* b_hh_l0  = (const float*)d_in[4];
    const float* w_ih_l0r = (const float*)d_in[5];
    const float* w_hh_l0r = (const float*)d_in[6];
    const float* b_ih_l0r = (const float*)d_in[7];
    const float* b_hh_l0r = (const float*)d_in[8];
    const float* w_ih_l1  = (const float*)d_in[9];
    const float* w_hh_l1  = (const float*)d_in[10];
    const float* b_ih_l1  = (const float*)d_in[11];
    const float* b_hh_l1  = (const float*)d_in[12];
    const float* w_ih_l1r = (const float*)d_in[13];
    const float* w_hh_l1r = (const float*)d_in[14];
    const float* b_ih_l1r = (const float*)d_in[15];
    const float* b_hh_l1r = (const float*)d_in[16];
    float* out = (float*)d_out;

    void* p;
    float *xt, *y0, *xg0, *xg1;
    void* hq;
    cudaGetSymbolAddress(&p, g_xt);   xt  = (float*)p;
    cudaGetSymbolAddress(&p, g_y0);   y0  = (float*)p;
    cudaGetSymbolAddress(&p, g_xg0);  xg0 = (float*)p;
    cudaGetSymbolAddress(&p, g_xg1);  xg1 = (float*)p;
    cudaGetSymbolAddress(&hq, g_hq);

    cudaFuncSetAttribute(lstm_rec, cudaFuncAttributeMaxDynamicSharedMemorySize,
                         REC_SMEM_BYTES);

    // clear stale tags from previous replays, then transpose x
    cudaMemsetAsync(hq, 0, sizeof(g_hq));
    transpose_x<<<dim3(Tz / 32, Iz / 32, Bz), dim3(32, 8)>>>(x);

    dim3 gg(Gz / 128, TB / 128);   // (16, 128)

    // ---- layer 0 (epoch 1) ----
    gemm_xg_mma<<<gg, 256>>>(xt, w_ih_l0,  b_ih_l0,  b_hh_l0,  xg0, Iz);
    gemm_xg_mma<<<gg, 256>>>(xt, w_ih_l0r, b_ih_l0r, b_hh_l0r, xg1, Iz);
    lstm_rec<<<128, 256, REC_SMEM_BYTES>>>(w_hh_l0, w_hh_l0r, y0,
                                           Bz * 2 * Hz, 2 * Hz, 1u);
    copy_state<<<128, 256>>>(out, 0);

    // ---- layer 1 (epoch 4096) ----
    gemm_xg_mma<<<gg, 256>>>(y0, w_ih_l1,  b_ih_l1,  b_hh_l1,  xg0, 2 * Hz);
    gemm_xg_mma<<<gg, 256>>>(y0, w_ih_l1r, b_ih_l1r, b_hh_l1r, xg1, 2 * Hz);
    lstm_rec<<<128, 256, REC_SMEM_BYTES>>>(w_hh_l1, w_hh_l1r, out,
                                           2 * Hz, Tz * 2 * Hz, 4096u);
    copy_state<<<128, 256>>>(out, 1);
}

// round 13
// speedup vs baseline: 2.5396x; 2.5396x over previous
#include <cuda_runtime.h>
#include <cuda_bf16.h>
#include <cstdint>

#define Tz 512
#define Bz 32
#define Iz 256
#define Hz 512
#define Gz 2048          // 4*H
#define TB (Tz*Bz)       // 16384

// -------- scratch (device globals; no runtime allocation) --------
__device__ float g_xt[(size_t)TB * Iz];        // x transposed to [T,B,I]
__device__ float g_xg0[(size_t)TB * Gz];       // fwd-dir input-gate projections
__device__ float g_xg1[(size_t)TB * Gz];       // bwd-dir input-gate projections
__device__ float g_y0[(size_t)TB * 2 * Hz];    // layer-0 output [T,B,2H]
__device__ unsigned g_hpk[2][2][Bz * Hz];      // [dir][parity][b*512+u] (bf16hi<<16)|bf16lo
__device__ float g_cbuf[2][Bz * Hz];           // [dir][b*H+u]
__device__ unsigned g_flag[2][64];             // per-CTA publish counters

__device__ __forceinline__ float sigf(float x) { return 1.f / (1.f + __expf(-x)); }
__device__ __forceinline__ float tanhf_(float x) { return 2.f / (1.f + __expf(-2.f * x)) - 1.f; }

__device__ __forceinline__ uint32_t f2tf32(float f) {
    uint32_t r;
    asm("cvt.rna.tf32.f32 %0, %1;" : "=r"(r) : "f"(f));
    return r;
}

__device__ __forceinline__ uint32_t smem_u32(const void* p) {
    uint32_t a;
    asm("{ .reg .u64 t; cvta.to.shared.u64 t, %1; cvt.u32.u64 %0, t; }" : "=r"(a) : "l"(p));
    return a;
}

// mma.sync tf32 m16n8k8 (input GEMMs)
__device__ __forceinline__ void mma_tf32(float* c, const uint32_t* a,
                                         uint32_t b0, uint32_t b1) {
    asm volatile(
        "mma.sync.aligned.m16n8k8.row.col.f32.tf32.tf32.f32 "
        "{%0,%1,%2,%3}, {%4,%5,%6,%7}, {%8,%9}, {%0,%1,%2,%3};"
        : "+f"(c[0]), "+f"(c[1]), "+f"(c[2]), "+f"(c[3])
        : "r"(a[0]), "r"(a[1]), "r"(a[2]), "r"(a[3]), "r"(b0), "r"(b1));
}

// mma.sync bf16 m16n8k16 (recurrence)
__device__ __forceinline__ void mma_bf16(float* c, const uint32_t* a,
                                         uint32_t b0, uint32_t b1) {
    asm volatile(
        "mma.sync.aligned.m16n8k16.row.col.f32.bf16.bf16.f32 "
        "{%0,%1,%2,%3}, {%4,%5,%6,%7}, {%8,%9}, {%0,%1,%2,%3};"
        : "+f"(c[0]), "+f"(c[1]), "+f"(c[2]), "+f"(c[3])
        : "r"(a[0]), "r"(a[1]), "r"(a[2]), "r"(a[3]), "r"(b0), "r"(b1));
}

#define LDSM2(d0, d1, a)                                                        \
    asm volatile("ldmatrix.sync.aligned.m8n8.x2.shared.b16 {%0,%1}, [%2];"      \
                 : "=r"(d0), "=r"(d1) : "r"(a))

// -------- transpose x [B,I,T] -> xt [T,B,I] --------
__global__ void transpose_x(const float* __restrict__ x) {
    __shared__ float tile[32][33];
    int b = blockIdx.z, i0 = blockIdx.y * 32, t0 = blockIdx.x * 32;
    int tx = threadIdx.x, ty = threadIdx.y;
#pragma unroll
    for (int r = ty; r < 32; r += 8)
        tile[r][tx] = x[(size_t)b * Iz * Tz + (size_t)(i0 + r) * Tz + t0 + tx];
    __syncthreads();
#pragma unroll
    for (int r = ty; r < 32; r += 8)
        g_xt[(size_t)(t0 + r) * Bz * Iz + (size_t)b * Iz + i0 + tx] = tile[tx][r];
}

// ======== tf32 mma.sync GEMM, both directions in one launch (blockIdx.z) =====
// Double-buffered SMEM stages: one __syncthreads per K-chunk; prefetch+store
// of chunk c+1 overlapped under chunk c's mma.
#define GSTG (128 * 36)
#define GEMM_SMEM_BYTES (4 * GSTG * 4)   // 2 stages x (As+Bs)

__global__ __launch_bounds__(256) void gemm_xg_mma(
    const float* __restrict__ A,
    const float* __restrict__ W0, const float* __restrict__ W1,
    const float* __restrict__ bi0, const float* __restrict__ bh0,
    const float* __restrict__ bi1, const float* __restrict__ bh1,
    float* __restrict__ C0, float* __restrict__ C1, int K)
{
    extern __shared__ uint32_t sg[];
    uint32_t* AsAll = sg;                 // [2][GSTG]
    uint32_t* BsAll = sg + 2 * GSTG;      // [2][GSTG]

    const float* W  = blockIdx.z ? W1  : W0;
    const float* bi = blockIdx.z ? bi1 : bi0;
    const float* bh = blockIdx.z ? bh1 : bh0;
    float* C        = blockIdx.z ? C1  : C0;

    int tid = threadIdx.x;
    int wid = tid >> 5, lane = tid & 31;
    int gid = lane >> 2, tig = lane & 3;
    int n0 = blockIdx.x * 128, m0 = blockIdx.y * 128;
    int mwarp = (wid >> 1) * 32;
    int nwarp = (wid & 1) * 64;
    int lrow = tid >> 3, lq = tid & 7;

    float c[2][8][4];
#pragma unroll
    for (int mt = 0; mt < 2; mt++)
#pragma unroll
        for (int nt = 0; nt < 8; nt++)
#pragma unroll
            for (int q = 0; q < 4; q++) c[mt][nt][q] = 0.f;

    float4 pa[4], pb[4];
#pragma unroll
    for (int j = 0; j < 4; j++) {
        pa[j] = *(const float4*)&A[(size_t)(m0 + lrow + j * 32) * K + lq * 4];
        pb[j] = *(const float4*)&W[(size_t)(n0 + lrow + j * 32) * K + lq * 4];
    }
    // store chunk 0 into stage 0
#pragma unroll
    for (int j = 0; j < 4; j++) {
        uint4 ta, tb;
        ta.x = f2tf32(pa[j].x); ta.y = f2tf32(pa[j].y);
        ta.z = f2tf32(pa[j].z); ta.w = f2tf32(pa[j].w);
        tb.x = f2tf32(pb[j].x); tb.y = f2tf32(pb[j].y);
        tb.z = f2tf32(pb[j].z); tb.w = f2tf32(pb[j].w);
        *(uint4*)&AsAll[(lrow + j * 32) * 36 + lq * 4] = ta;
        *(uint4*)&BsAll[(lrow + j * 32) * 36 + lq * 4] = tb;
    }
    __syncthreads();

    int nchunks = K >> 5;
    for (int ch = 0; ch < nchunks; ch++) {
        const uint32_t* As = AsAll + (ch & 1) * GSTG;
        const uint32_t* Bs = BsAll + (ch & 1) * GSTG;
        bool more = (ch + 1) < nchunks;
        if (more) {
            int k0 = (ch + 1) << 5;
#pragma unroll
            for (int j = 0; j < 4; j++) {
                pa[j] = *(const float4*)&A[(size_t)(m0 + lrow + j * 32) * K + k0 + lq * 4];
                pb[j] = *(const float4*)&W[(size_t)(n0 + lrow + j * 32) * K + k0 + lq * 4];
            }
        }

#pragma unroll
        for (int kk = 0; kk < 32; kk += 8) {
            uint32_t a[2][4];
#pragma unroll
            for (int mt = 0; mt < 2; mt++) {
                int mrow = mwarp + mt * 16;
                a[mt][0] = As[(mrow + gid)     * 36 + kk + tig];
                a[mt][1] = As[(mrow + gid + 8) * 36 + kk + tig];
                a[mt][2] = As[(mrow + gid)     * 36 + kk + tig + 4];
                a[mt][3] = As[(mrow + gid + 8) * 36 + kk + tig + 4];
            }
#pragma unroll
            for (int nt = 0; nt < 8; nt++) {
                uint32_t b0 = Bs[(nwarp + nt * 8 + gid) * 36 + kk + tig];
                uint32_t b1 = Bs[(nwarp + nt * 8 + gid) * 36 + kk + tig + 4];
                mma_tf32(c[0][nt], a[0], b0, b1);
                mma_tf32(c[1][nt], a[1], b0, b1);
            }
        }

        if (more) {
            uint32_t* An = AsAll + ((ch + 1) & 1) * GSTG;
            uint32_t* Bn = BsAll + ((ch + 1) & 1) * GSTG;
#pragma unroll
            for (int j = 0; j < 4; j++) {
                uint4 ta, tb;
                ta.x = f2tf32(pa[j].x); ta.y = f2tf32(pa[j].y);
                ta.z = f2tf32(pa[j].z); ta.w = f2tf32(pa[j].w);
                tb.x = f2tf32(pb[j].x); tb.y = f2tf32(pb[j].y);
                tb.z = f2tf32(pb[j].z); tb.w = f2tf32(pb[j].w);
                *(uint4*)&An[(lrow + j * 32) * 36 + lq * 4] = ta;
                *(uint4*)&Bn[(lrow + j * 32) * 36 + lq * 4] = tb;
            }
        }
        __syncthreads();
    }

#pragma unroll
    for (int mt = 0; mt < 2; mt++) {
        int m = m0 + mwarp + mt * 16 + gid;
#pragma unroll
        for (int nt = 0; nt < 8; nt++) {
            int n = n0 + nwarp + nt * 8 + 2 * tig;
            float bs0 = bi[n] + bh[n];
            float bs1 = bi[n + 1] + bh[n + 1];
            float2 o0 = {c[mt][nt][0] + bs0, c[mt][nt][1] + bs1};
            float2 o1 = {c[mt][nt][2] + bs0, c[mt][nt][3] + bs1};
            *(float2*)&C[(size_t)m * Gz + n] = o0;
            *(float2*)&C[(size_t)(m + 8) * Gz + n] = o1;
        }
    }
}

__global__ void reset_flags() {
    if (threadIdx.x < 128) ((unsigned*)g_flag)[threadIdx.x] = 0;
}

// ======== persistent recurrence — K-split bf16, direct-L2 fragment loads ========
// (R11 design, verbatim: flags + one-shot LDG.64 fragment loads, no SMEM bounce)
#define RST 1040                      // W smem row stride bytes (520 bf16)
#define RSM_WHI 0                     // [32 c][520]
#define RSM_WLO 33280
#define RSM_PS  66560                 // float[8][32][40]
#define REC_SMEM_BYTES (66560 + 8 * 32 * 40 * 4)

__global__ __launch_bounds__(256, 1) void lstm_rec(
    const float* __restrict__ Wf, const float* __restrict__ Wb,
    float* __restrict__ outbuf, int st_t, int st_b)
{
    extern __shared__ char smr[];
    uint32_t sbase = smem_u32(smr);

    int dir = blockIdx.x & 1;
    int cb = blockIdx.x >> 1;
    int u0 = cb * 8;
    const float* W = dir ? Wb : Wf;
    const float* xg = dir ? g_xg1 : g_xg0;
    int tid = threadIdx.x;
    int wid = tid >> 5, l = tid & 31;
    int gid = l >> 2, tig = l & 3;

    // ---- split this CTA's 32 W_hh rows into bf16 hi/lo SMEM planes (once) ----
    {
        int c = tid >> 3, kq = tid & 7;
        const float* wrow = W + (size_t)((c >> 3) * Hz + u0 + (c & 7)) * Hz;
        unsigned short* whi = (unsigned short*)(smr + RSM_WHI);
        unsigned short* wlo = (unsigned short*)(smr + RSM_WLO);
#pragma unroll 4
        for (int p = 0; p < 16; p++) {
            int k = p * 32 + kq * 4;
            float4 v = *(const float4*)&wrow[k];
            float vv[4] = {v.x, v.y, v.z, v.w};
#pragma unroll
            for (int j = 0; j < 4; j++) {
                __nv_bfloat16 hb = __float2bfloat16(vv[j]);
                whi[c * 520 + k + j] = __bfloat16_as_ushort(hb);
                wlo[c * 520 + k + j] = __bfloat16_as_ushort(
                    __float2bfloat16(vv[j] - __bfloat162float(hb)));
            }
        }
    }

    // ---- zero h parity-0 (this CTA's 1/64 slice), publish #1 ----
    g_hpk[dir][0][cb * 256 + tid] = 0u;
    float creg = 0.f;
    __syncthreads();
    if (tid == 0)
        asm volatile("red.release.gpu.global.add.u32 [%0], 1;"
                     :: "l"(&g_flag[dir][cb]) : "memory");

    // W-fragment ldmatrix base
    uint32_t bbase = sbase + RSM_WHI + (uint32_t)(l & 7) * RST
                   + (uint32_t)(((l >> 3) & 1) * 16) + (uint32_t)wid * 128;
    float* ps = (float*)(smr + RSM_PS);
    int bb = tid >> 3, uul = tid & 7;          // this thread's (batch, unit)

    // ---- hoist W fragments into registers (step-invariant) ----
    uint32_t wf[64];
#pragma unroll
    for (int ki = 0; ki < 4; ki++)
#pragma unroll
        for (int nt = 0; nt < 4; nt++) {
            LDSM2(wf[ki * 16 + nt * 4 + 0], wf[ki * 16 + nt * 4 + 1],
                  bbase + nt * 8 * RST + ki * 32);
            LDSM2(wf[ki * 16 + nt * 4 + 2], wf[ki * 16 + nt * 4 + 3],
                  bbase + 33280 + nt * 8 * RST + ki * 32);
        }

    // prefetch xg for step 0
    float xv[4];
    {
        int t0v = dir ? (Tz - 1) : 0;
        const float* xr = xg + (size_t)t0v * Bz * Gz + (size_t)bb * Gz + u0 + uul;
        xv[0] = xr[0 * Hz]; xv[1] = xr[1 * Hz]; xv[2] = xr[2 * Hz]; xv[3] = xr[3 * Hz];
    }

    const unsigned* myflag = &g_flag[dir][wid * 8 + (l & 7)];
    int kcb = wid * 64 + 2 * tig;              // this lane's base k column

    for (int s = 0; s < Tz; s++) {
        int rb = s & 1;
        int wb = rb ^ 1;
        int t = dir ? (Tz - 1 - s) : s;

        // ---- all lanes acquire-poll their producer flag (8 producers/warp) ----
        {
            unsigned tgt = (unsigned)(s + 1), v;
            do {
                asm volatile("ld.acquire.gpu.u32 %0, [%1];" : "=r"(v) : "l"(myflag) : "memory");
            } while (v < tgt);
        }

        // ---- direct-L2 A-fragment loads: 32x LDG.64 per warp (packed hi|lo) ----
        const unsigned* hp = g_hpk[dir][rb];
        uint2 wv[4][8];
#pragma unroll
        for (int ki = 0; ki < 4; ki++) {
            int kc = kcb + ki * 16;
#pragma unroll
            for (int mt = 0; mt < 2; mt++) {
                int r = mt * 16 + gid;
                wv[ki][mt * 4 + 0] = __ldcg((const uint2*)&hp[r * 512 + kc]);
                wv[ki][mt * 4 + 1] = __ldcg((const uint2*)&hp[(r + 8) * 512 + kc]);
                wv[ki][mt * 4 + 2] = __ldcg((const uint2*)&hp[r * 512 + kc + 8]);
                wv[ki][mt * 4 + 3] = __ldcg((const uint2*)&hp[(r + 8) * 512 + kc + 8]);
            }
        }

        // ---- partial gates: 32b x 32cols over this warp's k64, 3-mma split ----
        float c[2][4][4];
#pragma unroll
        for (int mt = 0; mt < 2; mt++)
#pragma unroll
            for (int nt = 0; nt < 4; nt++)
#pragma unroll
                for (int q = 0; q < 4; q++) c[mt][nt][q] = 0.f;

#pragma unroll
        for (int ki = 0; ki < 4; ki++) {
            uint32_t ah[8], al[8];
#pragma unroll
            for (int j = 0; j < 8; j++) {
                ah[j] = __byte_perm(wv[ki][j].x, wv[ki][j].y, 0x7632);
                al[j] = __byte_perm(wv[ki][j].x, wv[ki][j].y, 0x5410);
            }
#pragma unroll
            for (int nt = 0; nt < 4; nt++) {
                uint32_t bh0 = wf[ki * 16 + nt * 4 + 0];
                uint32_t bh1 = wf[ki * 16 + nt * 4 + 1];
                uint32_t bl0 = wf[ki * 16 + nt * 4 + 2];
                uint32_t bl1 = wf[ki * 16 + nt * 4 + 3];
                mma_bf16(c[0][nt], ah,     bh0, bh1);
                mma_bf16(c[1][nt], ah + 4, bh0, bh1);
                mma_bf16(c[0][nt], ah,     bl0, bl1);
                mma_bf16(c[1][nt], ah + 4, bl0, bl1);
                mma_bf16(c[0][nt], al,     bh0, bh1);
                mma_bf16(c[1][nt], al + 4, bh0, bh1);
            }
        }

        // ---- scatter partials to ps[wid][32][40] ----
        {
            float* pw = ps + wid * (32 * 40);
#pragma unroll
            for (int nt = 0; nt < 4; nt++) {
                int col = nt * 8 + 2 * tig;
                float2 v;
                v.x = c[0][nt][0]; v.y = c[0][nt][1];
                *(float2*)&pw[(gid)      * 40 + col] = v;
                v.x = c[0][nt][2]; v.y = c[0][nt][3];
                *(float2*)&pw[(gid + 8)  * 40 + col] = v;
                v.x = c[1][nt][0]; v.y = c[1][nt][1];
                *(float2*)&pw[(gid + 16) * 40 + col] = v;
                v.x = c[1][nt][2]; v.y = c[1][nt][3];
                *(float2*)&pw[(gid + 24) * 40 + col] = v;
            }
        }
        __syncthreads();

        // ---- reduce 8 partials + gates + state update (1 (b,u) per thread) ----
        float hn;
        {
            float gv4[4];
#pragma unroll
            for (int g = 0; g < 4; g++) {
                int base = bb * 40 + g * 8 + uul;
                float acc = xv[g];
#pragma unroll
                for (int w = 0; w < 8; w++) acc += ps[base + w * 1280];
                gv4[g] = acc;
            }
            float iv = sigf(gv4[0]), fv = sigf(gv4[1]);
            float gg = tanhf_(gv4[2]), ov = sigf(gv4[3]);
            float cn = fv * creg + iv * gg;
            hn = ov * tanhf_(cn);
            creg = cn;
            __nv_bfloat16 hb = __float2bfloat16(hn);
            unsigned hi = __bfloat16_as_ushort(hb);
            unsigned lo = __bfloat16_as_ushort(
                __float2bfloat16(hn - __bfloat162float(hb)));
            g_hpk[dir][wb][bb * 512 + u0 + uul] = (hi << 16) | lo;
        }

        // ---- publish h(s+1): release-atomic per-CTA flag bump ----
        __syncthreads();
        if (tid == 0)
            asm volatile("red.release.gpu.global.add.u32 [%0], 1;"
                         :: "l"(&g_flag[dir][cb]) : "memory");
        // off-critical-path: output store + next-step xg prefetch
        outbuf[(size_t)t * st_t + (size_t)bb * st_b + dir * Hz + u0 + uul] = hn;
        if (s + 1 < Tz) {
            int tn = dir ? (Tz - 2 - s) : (s + 1);
            const float* xr = xg + (size_t)tn * Bz * Gz + (size_t)bb * Gz + u0 + uul;
            xv[0] = xr[0 * Hz]; xv[1] = xr[1 * Hz];
            xv[2] = xr[2 * Hz]; xv[3] = xr[3 * Hz];
        }
    }

    g_cbuf[dir][bb * Hz + u0 + uul] = creg;
}

// -------- copy final h/c into h_n / c_n sections of d_out --------
__global__ void copy_state(float* __restrict__ dout, int layer) {
    int idx = blockIdx.x * 256 + threadIdx.x;   // 0..32767
    int d = idx >> 14;
    int r = idx & 16383;           // r = b*512 + u
    const size_t OUT = (size_t)Bz * Tz * 2 * Hz;
    unsigned w = g_hpk[d][0][r];
    float hv = __bfloat162float(__ushort_as_bfloat16((unsigned short)(w >> 16)))
             + __bfloat162float(__ushort_as_bfloat16((unsigned short)(w & 0xFFFFu)));
    dout[OUT + (size_t)(2 * layer + d) * (Bz * Hz) + r] = hv;
    dout[OUT + 4 * (size_t)(Bz * Hz) + (size_t)(2 * layer + d) * (Bz * Hz) + r] = g_cbuf[d][r];
}

extern "C" void kernel_launch(void* const* d_in, const int* in_sizes, int n_in,
                              void* d_out, int out_size)
{
    const float* x        = (const float*)d_in[0];
    const float* w_ih_l0  = (const float*)d_in[1];
    const float* w_hh_l0  = (const float*)d_in[2];
    const float* b_ih_l0  = (const float*)d_in[3];
    const float* b_hh_l0  = (const float*)d_in[4];
    const float* w_ih_l0r = (const float*)d_in[5];
    const float* w_hh_l0r = (const float*)d_in[6];
    const float* b_ih_l0r = (const float*)d_in[7];
    const float* b_hh_l0r = (const float*)d_in[8];
    const float* w_ih_l1  = (const float*)d_in[9];
    const float* w_hh_l1  = (const float*)d_in[10];
    const float* b_ih_l1  = (const float*)d_in[11];
    const float* b_hh_l1  = (const float*)d_in[12];
    const float* w_ih_l1r = (const float*)d_in[13];
    const float* w_hh_l1r = (const float*)d_in[14];
    const float* b_ih_l1r = (const float*)d_in[15];
    const float* b_hh_l1r = (const float*)d_in[16];
    float* out = (float*)d_out;

    void* p;
    float *xt, *y0, *xg0, *xg1;
    cudaGetSymbolAddress(&p, g_xt);   xt  = (float*)p;
    cudaGetSymbolAddress(&p, g_y0);   y0  = (float*)p;
    cudaGetSymbolAddress(&p, g_xg0);  xg0 = (float*)p;
    cudaGetSymbolAddress(&p, g_xg1);  xg1 = (float*)p;

    cudaFuncSetAttribute(lstm_rec, cudaFuncAttributeMaxDynamicSharedMemorySize,
                         REC_SMEM_BYTES);
    cudaFuncSetAttribute(gemm_xg_mma, cudaFuncAttributeMaxDynamicSharedMemorySize,
                         GEMM_SMEM_BYTES);

    // x [B,I,T] -> xt [T,B,I]
    transpose_x<<<dim3(Tz / 32, Iz / 32, Bz), dim3(32, 8)>>>(x);

    dim3 gg(Gz / 128, TB / 128, 2);   // (16, 128, 2) — both directions fused

    // ---- layer 0 ----
    gemm_xg_mma<<<gg, 256, GEMM_SMEM_BYTES>>>(
        xt, w_ih_l0, w_ih_l0r, b_ih_l0, b_hh_l0, b_ih_l0r, b_hh_l0r,
        xg0, xg1, Iz);
    reset_flags<<<1, 128>>>();
    lstm_rec<<<128, 256, REC_SMEM_BYTES>>>(w_hh_l0, w_hh_l0r, y0,
                                           Bz * 2 * Hz, 2 * Hz);
    copy_state<<<128, 256>>>(out, 0);

    // ---- layer 1 ----
    gemm_xg_mma<<<gg, 256, GEMM_SMEM_BYTES>>>(
        y0, w_ih_l1, w_ih_l1r, b_ih_l1, b_hh_l1, b_ih_l1r, b_hh_l1r,
        xg0, xg1, 2 * Hz);
    reset_flags<<<1, 128>>>();
    lstm_rec<<<128, 256, REC_SMEM_BYTES>>>(w_hh_l1, w_hh_l1r, out,
                                           2 * Hz, Tz * 2 * Hz);
    copy_state<<<128, 256>>>(out, 1);
}

// round 14
// speedup vs baseline: 2.5700x; 1.0120x over previous
#include <cuda_runtime.h>
#include <cuda_bf16.h>
#include <cstdint>

#define Tz 512
#define Bz 32
#define Iz 256
#define Hz 512
#define Gz 2048          // 4*H
#define TB (Tz*Bz)       // 16384

// -------- scratch (device globals; no runtime allocation) --------
__device__ float g_xt[(size_t)TB * Iz];        // x transposed to [T,B,I]
__device__ float g_xg0[(size_t)TB * Gz];       // fwd-dir input-gate projections
__device__ float g_xg1[(size_t)TB * Gz];       // bwd-dir input-gate projections
__device__ float g_y0[(size_t)TB * 2 * Hz];    // layer-0 output [T,B,2H]
__device__ unsigned g_hpk[2][2][Bz * Hz];      // [dir][parity][b*512+u] (hi<<16)|(lo&~3)|tag
__device__ unsigned g_flag[2][64];             // per-CTA publish counters

__device__ __forceinline__ float sigf(float x) { return 1.f / (1.f + __expf(-x)); }
__device__ __forceinline__ float tanhf_(float x) { return 2.f / (1.f + __expf(-2.f * x)) - 1.f; }

__device__ __forceinline__ uint32_t f2tf32(float f) {
    uint32_t r;
    asm("cvt.rna.tf32.f32 %0, %1;" : "=r"(r) : "f"(f));
    return r;
}

__device__ __forceinline__ uint32_t smem_u32(const void* p) {
    uint32_t a;
    asm("{ .reg .u64 t; cvta.to.shared.u64 t, %1; cvt.u32.u64 %0, t; }" : "=r"(a) : "l"(p));
    return a;
}

// mma.sync tf32 m16n8k8 (input GEMMs)
__device__ __forceinline__ void mma_tf32(float* c, const uint32_t* a,
                                         uint32_t b0, uint32_t b1) {
    asm volatile(
        "mma.sync.aligned.m16n8k8.row.col.f32.tf32.tf32.f32 "
        "{%0,%1,%2,%3}, {%4,%5,%6,%7}, {%8,%9}, {%0,%1,%2,%3};"
        : "+f"(c[0]), "+f"(c[1]), "+f"(c[2]), "+f"(c[3])
        : "r"(a[0]), "r"(a[1]), "r"(a[2]), "r"(a[3]), "r"(b0), "r"(b1));
}

// mma.sync bf16 m16n8k16 (recurrence)
__device__ __forceinline__ void mma_bf16(float* c, const uint32_t* a,
                                         uint32_t b0, uint32_t b1) {
    asm volatile(
        "mma.sync.aligned.m16n8k16.row.col.f32.bf16.bf16.f32 "
        "{%0,%1,%2,%3}, {%4,%5,%6,%7}, {%8,%9}, {%0,%1,%2,%3};"
        : "+f"(c[0]), "+f"(c[1]), "+f"(c[2]), "+f"(c[3])
        : "r"(a[0]), "r"(a[1]), "r"(a[2]), "r"(a[3]), "r"(b0), "r"(b1));
}

#define LDSM2(d0, d1, a)                                                        \
    asm volatile("ldmatrix.sync.aligned.m8n8.x2.shared.b16 {%0,%1}, [%2];"      \
                 : "=r"(d0), "=r"(d1) : "r"(a))

// -------- transpose x [B,I,T] -> xt [T,B,I] --------
__global__ void transpose_x(const float* __restrict__ x) {
    __shared__ float tile[32][33];
    int b = blockIdx.z, i0 = blockIdx.y * 32, t0 = blockIdx.x * 32;
    int tx = threadIdx.x, ty = threadIdx.y;
#pragma unroll
    for (int r = ty; r < 32; r += 8)
        tile[r][tx] = x[(size_t)b * Iz * Tz + (size_t)(i0 + r) * Tz + t0 + tx];
    __syncthreads();
#pragma unroll
    for (int r = ty; r < 32; r += 8)
        g_xt[(size_t)(t0 + r) * Bz * Iz + (size_t)b * Iz + i0 + tx] = tile[tx][r];
}

// ======== tf32 mma.sync GEMM: C[M,Gz] = A[M,K] @ W[Gz,K]^T + bi + bh ========
// (R11 version, verbatim — proven fastest GEMM config)
__global__ __launch_bounds__(256) void gemm_xg_mma(
    const float* __restrict__ A, const float* __restrict__ W,
    const float* __restrict__ bi, const float* __restrict__ bh,
    float* __restrict__ C, int K)
{
    __shared__ uint32_t As[128 * 36];
    __shared__ uint32_t Bs[128 * 36];

    int tid = threadIdx.x;
    int wid = tid >> 5, lane = tid & 31;
    int gid = lane >> 2, tig = lane & 3;
    int n0 = blockIdx.x * 128, m0 = blockIdx.y * 128;
    int mwarp = (wid >> 1) * 32;
    int nwarp = (wid & 1) * 64;
    int lrow = tid >> 3, lq = tid & 7;

    float c[2][8][4];
#pragma unroll
    for (int mt = 0; mt < 2; mt++)
#pragma unroll
        for (int nt = 0; nt < 8; nt++)
#pragma unroll
            for (int q = 0; q < 4; q++) c[mt][nt][q] = 0.f;

    float4 pa[4], pb[4];
#pragma unroll
    for (int j = 0; j < 4; j++) {
        pa[j] = *(const float4*)&A[(size_t)(m0 + lrow + j * 32) * K + lq * 4];
        pb[j] = *(const float4*)&W[(size_t)(n0 + lrow + j * 32) * K + lq * 4];
    }

    for (int k0 = 0; k0 < K; k0 += 32) {
#pragma unroll
        for (int j = 0; j < 4; j++) {
            uint4 ta, tb;
            ta.x = f2tf32(pa[j].x); ta.y = f2tf32(pa[j].y);
            ta.z = f2tf32(pa[j].z); ta.w = f2tf32(pa[j].w);
            tb.x = f2tf32(pb[j].x); tb.y = f2tf32(pb[j].y);
            tb.z = f2tf32(pb[j].z); tb.w = f2tf32(pb[j].w);
            *(uint4*)&As[(lrow + j * 32) * 36 + lq * 4] = ta;
            *(uint4*)&Bs[(lrow + j * 32) * 36 + lq * 4] = tb;
        }
        __syncthreads();

        if (k0 + 32 < K) {
#pragma unroll
            for (int j = 0; j < 4; j++) {
                pa[j] = *(const float4*)&A[(size_t)(m0 + lrow + j * 32) * K + k0 + 32 + lq * 4];
                pb[j] = *(const float4*)&W[(size_t)(n0 + lrow + j * 32) * K + k0 + 32 + lq * 4];
            }
        }

#pragma unroll
        for (int kk = 0; kk < 32; kk += 8) {
            uint32_t a[2][4];
#pragma unroll
            for (int mt = 0; mt < 2; mt++) {
                int mrow = mwarp + mt * 16;
                a[mt][0] = As[(mrow + gid)     * 36 + kk + tig];
                a[mt][1] = As[(mrow + gid + 8) * 36 + kk + tig];
                a[mt][2] = As[(mrow + gid)     * 36 + kk + tig + 4];
                a[mt][3] = As[(mrow + gid + 8) * 36 + kk + tig + 4];
            }
#pragma unroll
            for (int nt = 0; nt < 8; nt++) {
                uint32_t b0 = Bs[(nwarp + nt * 8 + gid) * 36 + kk + tig];
                uint32_t b1 = Bs[(nwarp + nt * 8 + gid) * 36 + kk + tig + 4];
                mma_tf32(c[0][nt], a[0], b0, b1);
                mma_tf32(c[1][nt], a[1], b0, b1);
            }
        }
        __syncthreads();
    }

#pragma unroll
    for (int mt = 0; mt < 2; mt++) {
        int m = m0 + mwarp + mt * 16 + gid;
#pragma unroll
        for (int nt = 0; nt < 8; nt++) {
            int n = n0 + nwarp + nt * 8 + 2 * tig;
            float bs0 = bi[n] + bh[n];
            float bs1 = bi[n + 1] + bh[n + 1];
            float2 o0 = {c[mt][nt][0] + bs0, c[mt][nt][1] + bs1};
            float2 o1 = {c[mt][nt][2] + bs0, c[mt][nt][3] + bs1};
            *(float2*)&C[(size_t)m * Gz + n] = o0;
            *(float2*)&C[(size_t)(m + 8) * Gz + n] = o1;
        }
    }
}

__global__ void reset_flags() {
    if (threadIdx.x < 128) ((unsigned*)g_flag)[threadIdx.x] = 0;
}

// ======== persistent recurrence — speculative tagged loads + flag fallback ======
// h word = (bf16hi<<16)|(bf16lo&~3)|tag, tag = layer*2 + ((step>>1)&1).
// Consumer loads fragments speculatively, checks tags; all-fresh -> no poll.
// Any stale -> acquire-poll producer flags, selectively reload stale elements.
#define RST 1040                      // W smem row stride bytes (520 bf16)
#define RSM_WHI 0                     // [32 c][520]
#define RSM_WLO 33280
#define RSM_PS  66560                 // float[8][32][40]
#define REC_SMEM_BYTES (66560 + 8 * 32 * 40 * 4)

__global__ __launch_bounds__(256, 1) void lstm_rec(
    const float* __restrict__ Wf, const float* __restrict__ Wb,
    float* __restrict__ outbuf, int st_t, int st_b,
    float* __restrict__ dout, int layer)
{
    extern __shared__ char smr[];
    uint32_t sbase = smem_u32(smr);

    int dir = blockIdx.x & 1;
    int cb = blockIdx.x >> 1;
    int u0 = cb * 8;
    const float* W = dir ? Wb : Wf;
    const float* xg = dir ? g_xg1 : g_xg0;
    int tid = threadIdx.x;
    int wid = tid >> 5, l = tid & 31;
    int gid = l >> 2, tig = l & 3;
    unsigned tagbase = (unsigned)layer * 2u;

    // ---- split this CTA's 32 W_hh rows into bf16 hi/lo SMEM planes (once) ----
    {
        int c = tid >> 3, kq = tid & 7;
        const float* wrow = W + (size_t)((c >> 3) * Hz + u0 + (c & 7)) * Hz;
        unsigned short* whi = (unsigned short*)(smr + RSM_WHI);
        unsigned short* wlo = (unsigned short*)(smr + RSM_WLO);
#pragma unroll 4
        for (int p = 0; p < 16; p++) {
            int k = p * 32 + kq * 4;
            float4 v = *(const float4*)&wrow[k];
            float vv[4] = {v.x, v.y, v.z, v.w};
#pragma unroll
            for (int j = 0; j < 4; j++) {
                __nv_bfloat16 hb = __float2bfloat16(vv[j]);
                whi[c * 520 + k + j] = __bfloat16_as_ushort(hb);
                wlo[c * 520 + k + j] = __bfloat16_as_ushort(
                    __float2bfloat16(vv[j] - __bfloat162float(hb)));
            }
        }
    }

    // ---- publish h(0) = 0 with tag (this CTA's 1/64 slice) ----
    g_hpk[dir][0][cb * 256 + tid] = tagbase;   // value 0, tag = tagbase
    float creg = 0.f;
    __syncthreads();
    if (tid == 0)
        asm volatile("red.release.gpu.global.add.u32 [%0], 1;"
                     :: "l"(&g_flag[dir][cb]) : "memory");

    // W-fragment ldmatrix base
    uint32_t bbase = sbase + RSM_WHI + (uint32_t)(l & 7) * RST
                   + (uint32_t)(((l >> 3) & 1) * 16) + (uint32_t)wid * 128;
    float* ps = (float*)(smr + RSM_PS);
    int bb = tid >> 3, uul = tid & 7;          // this thread's (batch, unit)

    // ---- hoist W fragments into registers (step-invariant) ----
    uint32_t wf[64];
#pragma unroll
    for (int ki = 0; ki < 4; ki++)
#pragma unroll
        for (int nt = 0; nt < 4; nt++) {
            LDSM2(wf[ki * 16 + nt * 4 + 0], wf[ki * 16 + nt * 4 + 1],
                  bbase + nt * 8 * RST + ki * 32);
            LDSM2(wf[ki * 16 + nt * 4 + 2], wf[ki * 16 + nt * 4 + 3],
                  bbase + 33280 + nt * 8 * RST + ki * 32);
        }

    // prefetch xg for step 0
    float xv[4];
    {
        int t0v = dir ? (Tz - 1) : 0;
        const float* xr = xg + (size_t)t0v * Bz * Gz + (size_t)bb * Gz + u0 + uul;
        xv[0] = xr[0 * Hz]; xv[1] = xr[1 * Hz]; xv[2] = xr[2 * Hz]; xv[3] = xr[3 * Hz];
    }

    const unsigned* myflag = &g_flag[dir][wid * 8 + (l & 7)];
    int kcb = wid * 64 + 2 * tig;              // this lane's base k column
    float hn = 0.f;

    for (int s = 0; s < Tz; s++) {
        int rb = s & 1;
        int wb = rb ^ 1;
        int t = dir ? (Tz - 1 - s) : s;
        unsigned rt = tagbase + (((unsigned)s >> 1) & 1);   // expected tag of h(s)

        // ---- speculative fragment loads + tag check ----
        const unsigned* hp = g_hpk[dir][rb];
        uint2 wv[4][8];
        unsigned stale = 0u;
#pragma unroll
        for (int ki = 0; ki < 4; ki++) {
            int kc = kcb + ki * 16;
#pragma unroll
            for (int mt = 0; mt < 2; mt++) {
                int r = mt * 16 + gid;
                wv[ki][mt * 4 + 0] = __ldcg((const uint2*)&hp[r * 512 + kc]);
                wv[ki][mt * 4 + 1] = __ldcg((const uint2*)&hp[(r + 8) * 512 + kc]);
                wv[ki][mt * 4 + 2] = __ldcg((const uint2*)&hp[r * 512 + kc + 8]);
                wv[ki][mt * 4 + 3] = __ldcg((const uint2*)&hp[(r + 8) * 512 + kc + 8]);
            }
        }
#pragma unroll
        for (int ki = 0; ki < 4; ki++)
#pragma unroll
            for (int j = 0; j < 8; j++) {
                unsigned bad = ((wv[ki][j].x ^ rt) | (wv[ki][j].y ^ rt)) & 3u;
                if (bad) stale |= 1u << (ki * 8 + j);
            }

        if (__any_sync(0xFFFFFFFFu, stale != 0u)) {
            // fallback: acquire-poll producer flags, selectively reload stale
            unsigned tgt = (unsigned)(s + 1), v;
            do {
                asm volatile("ld.acquire.gpu.u32 %0, [%1];" : "=r"(v) : "l"(myflag) : "memory");
            } while (v < tgt);
#pragma unroll
            for (int ki = 0; ki < 4; ki++) {
                int kc = kcb + ki * 16;
#pragma unroll
                for (int mt = 0; mt < 2; mt++) {
                    int r = mt * 16 + gid;
                    if (stale & (1u << (ki * 8 + mt * 4 + 0)))
                        wv[ki][mt * 4 + 0] = __ldcg((const uint2*)&hp[r * 512 + kc]);
                    if (stale & (1u << (ki * 8 + mt * 4 + 1)))
                        wv[ki][mt * 4 + 1] = __ldcg((const uint2*)&hp[(r + 8) * 512 + kc]);
                    if (stale & (1u << (ki * 8 + mt * 4 + 2)))
                        wv[ki][mt * 4 + 2] = __ldcg((const uint2*)&hp[r * 512 + kc + 8]);
                    if (stale & (1u << (ki * 8 + mt * 4 + 3)))
                        wv[ki][mt * 4 + 3] = __ldcg((const uint2*)&hp[(r + 8) * 512 + kc + 8]);
                }
            }
        }

        // ---- partial gates: 32b x 32cols over this warp's k64, 3-mma split ----
        float c[2][4][4];
#pragma unroll
        for (int mt = 0; mt < 2; mt++)
#pragma unroll
            for (int nt = 0; nt < 4; nt++)
#pragma unroll
                for (int q = 0; q < 4; q++) c[mt][nt][q] = 0.f;

#pragma unroll
        for (int ki = 0; ki < 4; ki++) {
            uint32_t ah[8], al[8];
#pragma unroll
            for (int j = 0; j < 8; j++) {
                ah[j] = __byte_perm(wv[ki][j].x, wv[ki][j].y, 0x7632);
                al[j] = __byte_perm(wv[ki][j].x, wv[ki][j].y, 0x5410);
            }
#pragma unroll
            for (int nt = 0; nt < 4; nt++) {
                uint32_t bh0 = wf[ki * 16 + nt * 4 + 0];
                uint32_t bh1 = wf[ki * 16 + nt * 4 + 1];
                uint32_t bl0 = wf[ki * 16 + nt * 4 + 2];
                uint32_t bl1 = wf[ki * 16 + nt * 4 + 3];
                mma_bf16(c[0][nt], ah,     bh0, bh1);
                mma_bf16(c[1][nt], ah + 4, bh0, bh1);
                mma_bf16(c[0][nt], ah,     bl0, bl1);
                mma_bf16(c[1][nt], ah + 4, bl0, bl1);
                mma_bf16(c[0][nt], al,     bh0, bh1);
                mma_bf16(c[1][nt], al + 4, bh0, bh1);
            }
        }

        // ---- scatter partials to ps[wid][32][40] ----
        {
            float* pw = ps + wid * (32 * 40);
#pragma unroll
            for (int nt = 0; nt < 4; nt++) {
                int col = nt * 8 + 2 * tig;
                float2 v;
                v.x = c[0][nt][0]; v.y = c[0][nt][1];
                *(float2*)&pw[(gid)      * 40 + col] = v;
                v.x = c[0][nt][2]; v.y = c[0][nt][3];
                *(float2*)&pw[(gid + 8)  * 40 + col] = v;
                v.x = c[1][nt][0]; v.y = c[1][nt][1];
                *(float2*)&pw[(gid + 16) * 40 + col] = v;
                v.x = c[1][nt][2]; v.y = c[1][nt][3];
                *(float2*)&pw[(gid + 24) * 40 + col] = v;
            }
        }
        __syncthreads();

        // ---- reduce 8 partials + gates + state update; store tagged h ----
        {
            float gv4[4];
#pragma unroll
            for (int g = 0; g < 4; g++) {
                int base = bb * 40 + g * 8 + uul;
                float acc = xv[g];
#pragma unroll
                for (int w = 0; w < 8; w++) acc += ps[base + w * 1280];
                gv4[g] = acc;
            }
            float iv = sigf(gv4[0]), fv = sigf(gv4[1]);
            float gg = tanhf_(gv4[2]), ov = sigf(gv4[3]);
            float cn = fv * creg + iv * gg;
            hn = ov * tanhf_(cn);
            creg = cn;
            __nv_bfloat16 hb = __float2bfloat16(hn);
            unsigned hi = __bfloat16_as_ushort(hb);
            unsigned lo = __bfloat16_as_ushort(
                __float2bfloat16(hn - __bfloat162float(hb)));
            unsigned wtag = tagbase + (((unsigned)(s + 1) >> 1) & 1);
            g_hpk[dir][wb][bb * 512 + u0 + uul] = (hi << 16) | (lo & 0xFFFCu) | wtag;
        }

        // ---- publish h(s+1): release-atomic per-CTA flag bump ----
        __syncthreads();
        if (tid == 0)
            asm volatile("red.release.gpu.global.add.u32 [%0], 1;"
                         :: "l"(&g_flag[dir][cb]) : "memory");
        // off-critical-path: output store + next-step xg prefetch
        outbuf[(size_t)t * st_t + (size_t)bb * st_b + dir * Hz + u0 + uul] = hn;
        if (s + 1 < Tz) {
            int tn = dir ? (Tz - 2 - s) : (s + 1);
            const float* xr = xg + (size_t)tn * Bz * Gz + (size_t)bb * Gz + u0 + uul;
            xv[0] = xr[0 * Hz]; xv[1] = xr[1 * Hz];
            xv[2] = xr[2 * Hz]; xv[3] = xr[3 * Hz];
        }
    }

    // ---- fused h_n / c_n epilogue (thread owns its final h and c) ----
    {
        const size_t OUT = (size_t)Bz * Tz * 2 * Hz;
        size_t r = (size_t)bb * Hz + u0 + uul;
        dout[OUT + (size_t)(2 * layer + dir) * (Bz * Hz) + r] = hn;
        dout[OUT + 4 * (size_t)(Bz * Hz) + (size_t)(2 * layer + dir) * (Bz * Hz) + r] = creg;
    }
}

extern "C" void kernel_launch(void* const* d_in, const int* in_sizes, int n_in,
                              void* d_out, int out_size)
{
    const float* x        = (const float*)d_in[0];
    const float* w_ih_l0  = (const float*)d_in[1];
    const float* w_hh_l0  = (const float*)d_in[2];
    const float* b_ih_l0  = (const float*)d_in[3];
    const float* b_hh_l0  = (const float*)d_in[4];
    const float* w_ih_l0r = (const float*)d_in[5];
    const float* w_hh_l0r = (const float*)d_in[6];
    const float* b_ih_l0r = (const float*)d_in[7];
    const float* b_hh_l0r = (const float*)d_in[8];
    const float* w_ih_l1  = (const float*)d_in[9];
    const float* w_hh_l1  = (const float*)d_in[10];
    const float* b_ih_l1  = (const float*)d_in[11];
    const float* b_hh_l1  = (const float*)d_in[12];
    const float* w_ih_l1r = (const float*)d_in[13];
    const float* w_hh_l1r = (const float*)d_in[14];
    const float* b_ih_l1r = (const float*)d_in[15];
    const float* b_hh_l1r = (const float*)d_in[16];
    float* out = (float*)d_out;

    void* p;
    float *xt, *y0, *xg0, *xg1;
    void* hq;
    cudaGetSymbolAddress(&p, g_xt);   xt  = (float*)p;
    cudaGetSymbolAddress(&p, g_y0);   y0  = (float*)p;
    cudaGetSymbolAddress(&p, g_xg0);  xg0 = (float*)p;
    cudaGetSymbolAddress(&p, g_xg1);  xg1 = (float*)p;
    cudaGetSymbolAddress(&hq, g_hpk);

    cudaFuncSetAttribute(lstm_rec, cudaFuncAttributeMaxDynamicSharedMemorySize,
                         REC_SMEM_BYTES);

    // invalidate stale h tags (tag bits -> 3, mismatching layer-0's expected 0)
    cudaMemsetAsync(hq, 0xFF, sizeof(g_hpk));
    transpose_x<<<dim3(Tz / 32, Iz / 32, Bz), dim3(32, 8)>>>(x);

    dim3 gg(Gz / 128, TB / 128);   // (16, 128)

    // ---- layer 0 ----
    gemm_xg_mma<<<gg, 256>>>(xt, w_ih_l0,  b_ih_l0,  b_hh_l0,  xg0, Iz);
    gemm_xg_mma<<<gg, 256>>>(xt, w_ih_l0r, b_ih_l0r, b_hh_l0r, xg1, Iz);
    reset_flags<<<1, 128>>>();
    lstm_rec<<<128, 256, REC_SMEM_BYTES>>>(w_hh_l0, w_hh_l0r, y0,
                                           Bz * 2 * Hz, 2 * Hz, out, 0);

    // ---- layer 1 ----
    gemm_xg_mma<<<gg, 256>>>(y0, w_ih_l1,  b_ih_l1,  b_hh_l1,  xg0, 2 * Hz);
    gemm_xg_mma<<<gg, 256>>>(y0, w_ih_l1r, b_ih_l1r, b_hh_l1r, xg1, 2 * Hz);
    reset_flags<<<1, 128>>>();
    lstm_rec<<<128, 256, REC_SMEM_BYTES>>>(w_hh_l1, w_hh_l1r, out,
                                           2 * Hz, Tz * 2 * Hz, out, 1);
}